// round 13
// baseline (speedup 1.0000x reference)
#include <cuda_runtime.h>
#include <cuda_fp16.h>
#include <mma.h>
#include <cstdint>

using namespace nvcuda;

#define NQ      4
#define DIM     16
#define NHEADS  8
#define NLAYERS 2
#define EMBED   32
#define NBASIS  81
#define KB      80               // features per head used by MMA (basis 1..80)
#define KPAD    88               // smem A row stride in halves
#define KSTEPS  5                // 5 x 16 = 80

// Per-head B operand ROW-MAJOR [k][n] fp16 (ld = 32): coalesced fragment loads.
__device__ half  g_B[NHEADS * KB * 32];
// Per-head constant term (basis k=0) folded out of the GEMM into the bias.
__device__ float g_biasH[NHEADS * EMBED];

// ---------------------------------------------------------------------------
// Precompute: per-head C pipeline (R8-validated), then:
//   g_B[h][k][n]   = sum_q C[h][k+1][q] * W_out[n][h*4+q]   (k = 0..79)
//   g_biasH[h][n]  = sum_q C[h][0][q]   * W_out[n][h*4+q]   (constant term)
// ---------------------------------------------------------------------------
__global__ void qmha_precompute(const float* __restrict__ params,
                                const float* __restrict__ W) {
    __shared__ float Ur[DIM][DIM];
    __shared__ float Ui[DIM][DIM];
    __shared__ float A[NQ][DIM * DIM];
    __shared__ float gc[NLAYERS * NQ * 3];
    __shared__ float gs[NLAYERS * NQ * 3];
    __shared__ float4 sC[NBASIS];

    const int h   = blockIdx.x;
    const int tid = threadIdx.x;

    if (tid < NLAYERS * NQ * 3) {
        const float th = params[h * NLAYERS * NQ * 3 + tid];
        float s, c;
        __sincosf(0.5f * th, &s, &c);
        gc[tid] = c;
        gs[tid] = s;
    }
    __syncthreads();

    if (tid < DIM) {
        float re[DIM], im[DIM];
        #pragma unroll
        for (int s = 0; s < DIM; s++) { re[s] = 0.f; im[s] = 0.f; }
        re[tid] = 1.f;

        for (int l = 0; l < NLAYERS; l++) {
            for (int w = 0; w < NQ; w++) {
                const int mask = 1 << (3 - w);
                const int gi = (l * NQ + w) * 3;
                const float cx = gc[gi + 0], sx = gs[gi + 0];
                const float cy = gc[gi + 1], sy = gs[gi + 1];
                const float cz = gc[gi + 2], sz = gs[gi + 2];
                #pragma unroll
                for (int s0 = 0; s0 < DIM; s0++) {
                    if (s0 & mask) continue;
                    const int s1 = s0 | mask;
                    float r0 = re[s0], i0 = im[s0], r1 = re[s1], i1 = im[s1];
                    float nr0 = cx * r0 + sx * i1;
                    float ni0 = cx * i0 - sx * r1;
                    float nr1 = sx * i0 + cx * r1;
                    float ni1 = -sx * r0 + cx * i1;
                    r0 = nr0; i0 = ni0; r1 = nr1; i1 = ni1;
                    nr0 = cy * r0 - sy * r1;
                    ni0 = cy * i0 - sy * i1;
                    nr1 = sy * r0 + cy * r1;
                    ni1 = sy * i0 + cy * i1;
                    r0 = nr0; i0 = ni0; r1 = nr1; i1 = ni1;
                    re[s0] = cz * r0 + sz * i0;
                    im[s0] = cz * i0 - sz * r0;
                    re[s1] = cz * r1 - sz * i1;
                    im[s1] = cz * i1 + sz * r1;
                }
            }
            #pragma unroll
            for (int e = 0; e < NQ; e++) {
                const int c = e, t = (e + 1) & 3;
                const int cm = 1 << (3 - c), tm = 1 << (3 - t);
                #pragma unroll
                for (int s = 0; s < DIM; s++) {
                    if ((s & cm) && !(s & tm)) {
                        const int s2 = s | tm;
                        float tr = re[s]; re[s] = re[s2]; re[s2] = tr;
                        float ti = im[s]; im[s] = im[s2]; im[s2] = ti;
                    }
                }
            }
        }
        #pragma unroll
        for (int s = 0; s < DIM; s++) { Ur[tid][s] = re[s]; Ui[tid][s] = im[s]; }
    }
    __syncthreads();

    {
        const int p = tid >> 4, q = tid & 15;
        float a0 = 0.f, a1 = 0.f, a2 = 0.f, a3 = 0.f;
        #pragma unroll
        for (int s = 0; s < DIM; s++) {
            float rr = Ur[p][s] * Ur[q][s] + Ui[p][s] * Ui[q][s];
            a0 += (s & 8) ? -rr : rr;
            a1 += (s & 4) ? -rr : rr;
            a2 += (s & 2) ? -rr : rr;
            a3 += (s & 1) ? -rr : rr;
        }
        A[0][tid] = a0; A[1][tid] = a1; A[2][tid] = a2; A[3][tid] = a3;
    }
    __syncthreads();

    if (tid < NBASIS) {
        int kw[4] = {tid / 27, (tid / 9) % 3, (tid / 3) % 3, tid % 3};
        float acc0 = 0.f, acc1 = 0.f, acc2 = 0.f, acc3 = 0.f;
        #pragma unroll
        for (int m = 0; m < 16; m++) {
            int p = 0, q = 0;
            float wgt = 1.0f / 16.0f;
            #pragma unroll
            for (int w = 0; w < 4; w++) {
                const int opt = (m >> w) & 1;
                const int kk = kw[w];
                int a, bb;
                if (kk == 0)      { a = opt; bb = opt; }
                else if (kk == 1) { a = opt; bb = opt; if (opt) wgt = -wgt; }
                else              { a = opt; bb = 1 - opt; }
                p |= a << (3 - w);
                q |= bb << (3 - w);
            }
            acc0 += wgt * A[0][p * 16 + q];
            acc1 += wgt * A[1][p * 16 + q];
            acc2 += wgt * A[2][p * 16 + q];
            acc3 += wgt * A[3][p * 16 + q];
        }
        sC[tid] = make_float4(acc0, acc1, acc2, acc3);
    }
    __syncthreads();

    // B row-major [k][n], k = basis 1..80
    for (int idx = tid; idx < KB * 32; idx += 256) {
        const int k = idx >> 5, n = idx & 31;
        const float4 c = sC[k + 1];
        const float* wr = W + n * 32 + h * 4;   // W_out[n][h*4 + q]
        const float m = c.x * wr[0] + c.y * wr[1] + c.z * wr[2] + c.w * wr[3];
        g_B[h * KB * 32 + idx] = __float2half_rn(m);
    }
    // constant-term bias contribution (basis k=0 has feature value 1)
    if (tid < EMBED) {
        const float4 c0 = sC[0];
        const float* wr = W + tid * 32 + h * 4;
        g_biasH[h * EMBED + tid] =
            c0.x * wr[0] + c0.y * wr[1] + c0.z * wr[2] + c0.w * wr[3];
    }
}

// ---------------------------------------------------------------------------
// Main: 128 tokens/block, 4 warps, 6 blocks/SM. Per head: threads build 80
// fp16 features into the smem A-tile; warps run wmma m16n16k16 (2 M x 2 N x
// 5 K) with B loaded ROW-MAJOR straight from global (coalesced, L1-cached).
// Exact f32 bias (incl. folded constant terms) in the epilogue.
// ---------------------------------------------------------------------------
#define BIAS_OFF 0
#define A_OFF    128
#define SMEM_TOTAL (A_OFF + 128 * KPAD * 2)   // 22656 B

__global__ __launch_bounds__(128, 6) void qmha_tc(
    const float4* __restrict__ x,
    float4*       __restrict__ out,
    const float*  __restrict__ bglob)
{
    extern __shared__ char smem[];
    const int tid  = threadIdx.x;
    const int warp = tid >> 5;

    if (tid < EMBED) {
        float s = bglob[tid];
        #pragma unroll
        for (int h = 0; h < NHEADS; h++) s += g_biasH[h * EMBED + tid];
        ((float*)(smem + BIAS_OFF))[tid] = s;
    }
    __syncthreads();

    const int t = blockIdx.x * 128 + tid;

    wmma::fragment<wmma::accumulator, 16, 16, 16, float> acc[2][2];
    #pragma unroll
    for (int mt = 0; mt < 2; mt++)
        #pragma unroll
        for (int nt = 0; nt < 2; nt++)
            wmma::fill_fragment(acc[mt][nt], 0.f);

    half* As = (half*)(smem + A_OFF);

    #pragma unroll 1
    for (int h = 0; h < NHEADS; h++) {
        const float4 xv = x[t * 8 + h];
        float c0, s0, c1, s1, c2, s2, c3, s3;
        __sincosf(xv.x, &s0, &c0); __sincosf(xv.y, &s1, &c1);
        __sincosf(xv.z, &s2, &c2); __sincosf(xv.w, &s3, &c3);

        const float A9[9] = {1.f, c1, s1, c0, c0 * c1, c0 * s1, s0, s0 * c1, s0 * s1};
        const float B9[9] = {1.f, c3, s3, c2, c2 * c3, c2 * s3, s2, s2 * c3, s2 * s3};

        // build features f=0..79 (basis k=f+1) in 10 chunks of 8 -> low live regs
        {
            float4* row = (float4*)(As + tid * KPAD);
            #pragma unroll
            for (int c = 0; c < 10; c++) {
                uint32_t u[4];
                #pragma unroll
                for (int e = 0; e < 4; e++) {
                    const int k0 = 8 * c + 2 * e + 1;
                    const int k1 = k0 + 1;
                    const __half2 hh = __floats2half2_rn(A9[k0 / 9] * B9[k0 % 9],
                                                         A9[k1 / 9] * B9[k1 % 9]);
                    u[e] = *(const uint32_t*)&hh;
                }
                row[c] = make_float4(__uint_as_float(u[0]), __uint_as_float(u[1]),
                                     __uint_as_float(u[2]), __uint_as_float(u[3]));
            }
        }
        __syncthreads();

        const half* Bh = g_B + h * KB * 32;   // row-major [k][n], ld=32
        #pragma unroll
        for (int ks = 0; ks < KSTEPS; ks++) {
            wmma::fragment<wmma::matrix_a, 16, 16, 16, half, wmma::row_major> af[2];
            wmma::fragment<wmma::matrix_b, 16, 16, 16, half, wmma::row_major> bf[2];
            wmma::load_matrix_sync(af[0], As + (warp * 32 +  0) * KPAD + ks * 16, KPAD);
            wmma::load_matrix_sync(af[1], As + (warp * 32 + 16) * KPAD + ks * 16, KPAD);
            wmma::load_matrix_sync(bf[0], Bh + ks * 16 * 32 +  0, 32);
            wmma::load_matrix_sync(bf[1], Bh + ks * 16 * 32 + 16, 32);
            #pragma unroll
            for (int mt = 0; mt < 2; mt++)
                #pragma unroll
                for (int nt = 0; nt < 2; nt++)
                    wmma::mma_sync(acc[mt][nt], af[mt], bf[nt], acc[mt][nt]);
        }
        __syncthreads();   // A-tile reused next head
    }

    // epilogue: fragments -> smem f32 (ld=40), + exact bias, -> global
    float* Cs = (float*)(smem + A_OFF);   // 128 x 40 f32 = 20.5 KB (fits A region)
    #pragma unroll
    for (int mt = 0; mt < 2; mt++)
        #pragma unroll
        for (int nt = 0; nt < 2; nt++)
            wmma::store_matrix_sync(Cs + (warp * 32 + mt * 16) * 40 + nt * 16,
                                    acc[mt][nt], 40, wmma::mem_row_major);
    __syncthreads();

    {
        const float4* bs4 = (const float4*)(smem + BIAS_OFF);
        const float* crow = Cs + tid * 40;
        #pragma unroll
        for (int e4 = 0; e4 < 8; e4++) {
            const float4 bv = bs4[e4];
            out[t * 8 + e4] = make_float4(crow[4 * e4 + 0] + bv.x,
                                          crow[4 * e4 + 1] + bv.y,
                                          crow[4 * e4 + 2] + bv.z,
                                          crow[4 * e4 + 3] + bv.w);
        }
    }
}

extern "C" void kernel_launch(void* const* d_in, const int* in_sizes, int n_in,
                              void* d_out, int out_size) {
    const float* x      = (const float*)d_in[0];
    const float* params = (const float*)d_in[1];
    const float* W      = (const float*)d_in[2];
    const float* b      = (const float*)d_in[3];

    const int tokens = in_sizes[0] / EMBED;   // 131072

    cudaFuncSetAttribute(qmha_tc, cudaFuncAttributeMaxDynamicSharedMemorySize, SMEM_TOTAL);

    qmha_precompute<<<NHEADS, 256>>>(params, W);

    const int blocks = tokens / 128;          // 1024
    qmha_tc<<<blocks, 128, SMEM_TOTAL>>>((const float4*)x, (float4*)d_out, b);
}

// round 14
// speedup vs baseline: 1.3290x; 1.3290x over previous
#include <cuda_runtime.h>
#include <cuda_fp16.h>
#include <cstdint>

#define NQ      4
#define DIM     16
#define NHEADS  8
#define NLAYERS 2
#define EMBED   32
#define NBASIS  81
#define KS      6                // 6 k-steps of 16 -> K=96 (12 slots)
#define NT      4                // 4 n-tiles of 8 -> N=32

// B operand pre-linearized in m16n8k16 fragment order:
// g_Bf[((h*KS+ks)*NT+nt)*32 + lane] = {x: half2(M[k0][n],M[k0+1][n]),
//                                      y: half2(M[k0+8][n],M[k0+9][n])}
// with k0 = ks*16 + 2*(lane%4), n = nt*8 + lane/4.
__device__ uint2 g_Bf[NHEADS * KS * NT * 32];

// pack two f32 -> f16x2 (lo = first arg)
__device__ __forceinline__ uint32_t f2h2(float lo, float hi) {
    uint32_t r;
    asm("cvt.rn.f16x2.f32 %0, %1, %2;" : "=r"(r) : "f"(hi), "f"(lo));
    return r;
}

__device__ __forceinline__ void mma16816(float& d0, float& d1, float& d2, float& d3,
                                         uint32_t a0, uint32_t a1, uint32_t a2, uint32_t a3,
                                         uint32_t b0, uint32_t b1) {
    asm("mma.sync.aligned.m16n8k16.row.col.f32.f16.f16.f32 "
        "{%0,%1,%2,%3}, {%4,%5,%6,%7}, {%8,%9}, {%0,%1,%2,%3};"
        : "+f"(d0), "+f"(d1), "+f"(d2), "+f"(d3)
        : "r"(a0), "r"(a1), "r"(a2), "r"(a3), "r"(b0), "r"(b1));
}

// ---------------------------------------------------------------------------
// Precompute: per-head C pipeline (validated since R8), then emit B in
// fragment order under the slot basis-reordering:
//   position k = 16ks + 8dh + 2m + e, slot = 2ks+dh:
//     slot<=8 : basis b = 9*slot + (2m+e)                       (j = 0..7)
//     slot>=9 : p = slot-9; q = (m==0)? e : (m==1 && e==0)? 2 : none
//               basis b = 9*(3p+q) + 8                          (j = 8)
// ---------------------------------------------------------------------------
__global__ void qmha_precompute(const float* __restrict__ params,
                                const float* __restrict__ W) {
    __shared__ float Ur[DIM][DIM];
    __shared__ float Ui[DIM][DIM];
    __shared__ float A[NQ][DIM * DIM];
    __shared__ float gc[NLAYERS * NQ * 3];
    __shared__ float gs[NLAYERS * NQ * 3];
    __shared__ float4 sC[NBASIS];

    const int h   = blockIdx.x;
    const int tid = threadIdx.x;

    if (tid < NLAYERS * NQ * 3) {
        const float th = params[h * NLAYERS * NQ * 3 + tid];
        float s, c;
        __sincosf(0.5f * th, &s, &c);
        gc[tid] = c;
        gs[tid] = s;
    }
    __syncthreads();

    if (tid < DIM) {
        float re[DIM], im[DIM];
        #pragma unroll
        for (int s = 0; s < DIM; s++) { re[s] = 0.f; im[s] = 0.f; }
        re[tid] = 1.f;

        for (int l = 0; l < NLAYERS; l++) {
            for (int w = 0; w < NQ; w++) {
                const int mask = 1 << (3 - w);
                const int gi = (l * NQ + w) * 3;
                const float cx = gc[gi + 0], sx = gs[gi + 0];
                const float cy = gc[gi + 1], sy = gs[gi + 1];
                const float cz = gc[gi + 2], sz = gs[gi + 2];
                #pragma unroll
                for (int s0 = 0; s0 < DIM; s0++) {
                    if (s0 & mask) continue;
                    const int s1 = s0 | mask;
                    float r0 = re[s0], i0 = im[s0], r1 = re[s1], i1 = im[s1];
                    float nr0 = cx * r0 + sx * i1;
                    float ni0 = cx * i0 - sx * r1;
                    float nr1 = sx * i0 + cx * r1;
                    float ni1 = -sx * r0 + cx * i1;
                    r0 = nr0; i0 = ni0; r1 = nr1; i1 = ni1;
                    nr0 = cy * r0 - sy * r1;
                    ni0 = cy * i0 - sy * i1;
                    nr1 = sy * r0 + cy * r1;
                    ni1 = sy * i0 + cy * i1;
                    r0 = nr0; i0 = ni0; r1 = nr1; i1 = ni1;
                    re[s0] = cz * r0 + sz * i0;
                    im[s0] = cz * i0 - sz * r0;
                    re[s1] = cz * r1 - sz * i1;
                    im[s1] = cz * i1 + sz * r1;
                }
            }
            #pragma unroll
            for (int e = 0; e < NQ; e++) {
                const int c = e, t = (e + 1) & 3;
                const int cm = 1 << (3 - c), tm = 1 << (3 - t);
                #pragma unroll
                for (int s = 0; s < DIM; s++) {
                    if ((s & cm) && !(s & tm)) {
                        const int s2 = s | tm;
                        float tr = re[s]; re[s] = re[s2]; re[s2] = tr;
                        float ti = im[s]; im[s] = im[s2]; im[s2] = ti;
                    }
                }
            }
        }
        #pragma unroll
        for (int s = 0; s < DIM; s++) { Ur[tid][s] = re[s]; Ui[tid][s] = im[s]; }
    }
    __syncthreads();

    {
        const int p = tid >> 4, q = tid & 15;
        float a0 = 0.f, a1 = 0.f, a2 = 0.f, a3 = 0.f;
        #pragma unroll
        for (int s = 0; s < DIM; s++) {
            float rr = Ur[p][s] * Ur[q][s] + Ui[p][s] * Ui[q][s];
            a0 += (s & 8) ? -rr : rr;
            a1 += (s & 4) ? -rr : rr;
            a2 += (s & 2) ? -rr : rr;
            a3 += (s & 1) ? -rr : rr;
        }
        A[0][tid] = a0; A[1][tid] = a1; A[2][tid] = a2; A[3][tid] = a3;
    }
    __syncthreads();

    if (tid < NBASIS) {
        int kw[4] = {tid / 27, (tid / 9) % 3, (tid / 3) % 3, tid % 3};
        float acc0 = 0.f, acc1 = 0.f, acc2 = 0.f, acc3 = 0.f;
        #pragma unroll
        for (int mm = 0; mm < 16; mm++) {
            int p = 0, q = 0;
            float wgt = 1.0f / 16.0f;
            #pragma unroll
            for (int w = 0; w < 4; w++) {
                const int opt = (mm >> w) & 1;
                const int kk = kw[w];
                int a, bb;
                if (kk == 0)      { a = opt; bb = opt; }
                else if (kk == 1) { a = opt; bb = opt; if (opt) wgt = -wgt; }
                else              { a = opt; bb = 1 - opt; }
                p |= a << (3 - w);
                q |= bb << (3 - w);
            }
            acc0 += wgt * A[0][p * 16 + q];
            acc1 += wgt * A[1][p * 16 + q];
            acc2 += wgt * A[2][p * 16 + q];
            acc3 += wgt * A[3][p * 16 + q];
        }
        sC[tid] = make_float4(acc0, acc1, acc2, acc3);
    }
    __syncthreads();

    // Emit fragment-ordered B
    for (int e = tid; e < KS * NT * 32; e += 256) {
        const int ks = e >> 7;
        const int nt = (e >> 5) & 3;
        const int lane = e & 31;
        const int m = lane & 3, g = lane >> 2;
        const int n = nt * 8 + g;
        const float* wr = W + n * 32 + h * 4;   // W_out[n][h*4+q]

        float v[2][2];
        #pragma unroll
        for (int dh = 0; dh < 2; dh++) {
            #pragma unroll
            for (int eps = 0; eps < 2; eps++) {
                const int slot = 2 * ks + dh;
                float val = 0.f;
                if (slot <= 8) {
                    const int b = 9 * slot + (2 * m + eps);
                    const float4 c = sC[b];
                    val = c.x * wr[0] + c.y * wr[1] + c.z * wr[2] + c.w * wr[3];
                } else {
                    const int p = slot - 9;
                    const int q = (m == 0) ? eps : ((m == 1 && eps == 0) ? 2 : -1);
                    if (q >= 0) {
                        const float4 c = sC[9 * (3 * p + q) + 8];
                        val = c.x * wr[0] + c.y * wr[1] + c.z * wr[2] + c.w * wr[3];
                    }
                }
                v[dh][eps] = val;
            }
        }
        g_Bf[((h * KS + ks) * NT + nt) * 32 + lane] =
            make_uint2(f2h2(v[0][0], v[0][1]), f2h2(v[1][0], v[1][1]));
    }
}

// Build the 12 slot registers for one token from its c[4], s[4] (per-lane m).
__device__ __forceinline__ void build_slots(const float* c, const float* s, int m,
                                            uint32_t* S) {
    const float c2c3 = c[2] * c[3], c2s3 = c[2] * s[3];
    const float s2c3 = s[2] * c[3], s2s3 = s[2] * s[3];
    // P = (B9[2m], B9[2m+1]); B9 = {1,c3,s3,c2,c2c3,c2s3,s2,s2c3,s2s3}
    const float Px = (m & 2) ? ((m & 1) ? s[2] : c2c3) : ((m & 1) ? s[3] : 1.f);
    const float Py = (m & 2) ? ((m & 1) ? s2c3 : c2s3) : ((m & 1) ? c[2] : c[3]);
    // Q covers the j=8 column: (f1[q]*s2s3) pairs
    const float Qx = (m & 2) ? 0.f : ((m & 1) ? s[1] * s2s3 : s2s3);
    const float Qy = (m == 0) ? c[1] * s2s3 : 0.f;

    const float A9[9] = {1.f, c[1], s[1], c[0], c[0] * c[1], c[0] * s[1],
                         s[0], s[0] * c[1], s[0] * s[1]};
    #pragma unroll
    for (int i = 0; i < 9; i++) S[i] = f2h2(A9[i] * Px, A9[i] * Py);
    S[9]  = f2h2(Qx, Qy);
    S[10] = f2h2(c[0] * Qx, c[0] * Qy);
    S[11] = f2h2(s[0] * Qx, s[0] * Qy);
}

// ---------------------------------------------------------------------------
// Main: NO shared memory, NO barriers. Each warp owns 16 tokens.
// Lane l: tokens tA = tbase + l/4 (rows 0-7), tB = tA+8 (rows 8-15).
// A fragments built in registers; B fragments one coalesced LDG.64 each.
// ---------------------------------------------------------------------------
__global__ __launch_bounds__(128, 4) void qmha_mma(
    const float4* __restrict__ x,
    float*        __restrict__ out,
    const float*  __restrict__ bias)
{
    const int lane = threadIdx.x & 31;
    const int warp = threadIdx.x >> 5;
    const int m = lane & 3, g = lane >> 2;
    const int tbase = blockIdx.x * 64 + warp * 16;
    const int tA = tbase + g, tB = tA + 8;
    const int srcbase = lane & ~3;

    float acc[NT][4];
    #pragma unroll
    for (int nt = 0; nt < NT; nt++)
        #pragma unroll
        for (int r = 0; r < 4; r++) acc[nt][r] = 0.f;

    #pragma unroll 1
    for (int h = 0; h < NHEADS; h++) {
        const float4 xA = x[tA * 8 + h];
        const float4 xB = x[tB * 8 + h];

        // each lane does the sincos of angle index m for both tokens, then
        // the 4-lane group exchanges so everyone has all 4 (c,s) pairs.
        const float angA = (m == 0) ? xA.x : (m == 1) ? xA.y : (m == 2) ? xA.z : xA.w;
        const float angB = (m == 0) ? xB.x : (m == 1) ? xB.y : (m == 2) ? xB.z : xB.w;
        float coA, soA, coB, soB;
        __sincosf(angA, &soA, &coA);
        __sincosf(angB, &soB, &coB);

        float cA[4], sA[4], cB[4], sB[4];
        #pragma unroll
        for (int j = 0; j < 4; j++) {
            cA[j] = __shfl_sync(0xffffffffu, coA, srcbase + j);
            sA[j] = __shfl_sync(0xffffffffu, soA, srcbase + j);
            cB[j] = __shfl_sync(0xffffffffu, coB, srcbase + j);
            sB[j] = __shfl_sync(0xffffffffu, soB, srcbase + j);
        }

        uint32_t SA[12], SB[12];
        build_slots(cA, sA, m, SA);
        build_slots(cB, sB, m, SB);

        const uint2* Bf = g_Bf + (h * KS * NT) * 32 + lane;
        #pragma unroll
        for (int ks = 0; ks < KS; ks++) {
            #pragma unroll
            for (int nt = 0; nt < NT; nt++) {
                const uint2 bf = __ldg(Bf + (ks * NT + nt) * 32);
                mma16816(acc[nt][0], acc[nt][1], acc[nt][2], acc[nt][3],
                         SA[2 * ks], SB[2 * ks], SA[2 * ks + 1], SB[2 * ks + 1],
                         bf.x, bf.y);
            }
        }
    }

    // epilogue: D layout c0,c1 = (row g,   cols nt*8+2m,+1)
    //                    c2,c3 = (row g+8, cols nt*8+2m,+1)
    #pragma unroll
    for (int nt = 0; nt < NT; nt++) {
        const int n0 = nt * 8 + 2 * m;
        const float2 bv = *(const float2*)(bias + n0);
        float2 oA; oA.x = acc[nt][0] + bv.x; oA.y = acc[nt][1] + bv.y;
        float2 oB; oB.x = acc[nt][2] + bv.x; oB.y = acc[nt][3] + bv.y;
        *(float2*)(out + tA * 32 + n0) = oA;
        *(float2*)(out + tB * 32 + n0) = oB;
    }
}

extern "C" void kernel_launch(void* const* d_in, const int* in_sizes, int n_in,
                              void* d_out, int out_size) {
    const float* x      = (const float*)d_in[0];
    const float* params = (const float*)d_in[1];
    const float* W      = (const float*)d_in[2];
    const float* b      = (const float*)d_in[3];

    const int tokens = in_sizes[0] / EMBED;   // 131072

    qmha_precompute<<<NHEADS, 256>>>(params, W);

    const int blocks = tokens / 64;           // 2048 (64 tokens per 128-thr block)
    qmha_mma<<<blocks, 128>>>((const float4*)x, (float*)d_out, b);
}

// round 15
// speedup vs baseline: 1.6713x; 1.2575x over previous
#include <cuda_runtime.h>
#include <cuda_fp16.h>
#include <cstdint>

#define NQ      4
#define DIM     16
#define NHEADS  8
#define NLAYERS 2
#define EMBED   32
#define NBASIS  81
#define KS      6                // 6 k-steps of 16 -> K=96 (12 slots)

// B operand in m16n8k16 fragment order, packed as uint4 covering an nt-PAIR:
// g_Bf4[(h*KS+ks)*2*32 + np*32 + lane] =
//   {x: half2(b0 of nt=2np), y: half2(b1 of nt=2np),
//    z: half2(b0 of nt=2np+1), w: half2(b1 of nt=2np+1)}
// where b0 = (M[k0][n],M[k0+1][n]), b1 = (M[k0+8][n],M[k0+9][n]),
// k0 = ks*16 + 2*(lane%4), n = nt*8 + lane/4.
__device__ uint4 g_Bf4[NHEADS * KS * 2 * 32];

// pack two f32 -> f16x2 (lo = first arg)
__device__ __forceinline__ uint32_t f2h2(float lo, float hi) {
    uint32_t r;
    asm("cvt.rn.f16x2.f32 %0, %1, %2;" : "=r"(r) : "f"(hi), "f"(lo));
    return r;
}

__device__ __forceinline__ void mma16816(float& d0, float& d1, float& d2, float& d3,
                                         uint32_t a0, uint32_t a1, uint32_t a2, uint32_t a3,
                                         uint32_t b0, uint32_t b1) {
    asm("mma.sync.aligned.m16n8k16.row.col.f32.f16.f16.f32 "
        "{%0,%1,%2,%3}, {%4,%5,%6,%7}, {%8,%9}, {%0,%1,%2,%3};"
        : "+f"(d0), "+f"(d1), "+f"(d2), "+f"(d3)
        : "r"(a0), "r"(a1), "r"(a2), "r"(a3), "r"(b0), "r"(b1));
}

// ---------------------------------------------------------------------------
// Precompute: per-head C pipeline (validated R8-R14), then emit B in the
// uint4 nt-pair fragment layout under the R14 slot basis-reordering.
// ---------------------------------------------------------------------------
__global__ void qmha_precompute(const float* __restrict__ params,
                                const float* __restrict__ W) {
    __shared__ float Ur[DIM][DIM];
    __shared__ float Ui[DIM][DIM];
    __shared__ float A[NQ][DIM * DIM];
    __shared__ float gc[NLAYERS * NQ * 3];
    __shared__ float gs[NLAYERS * NQ * 3];
    __shared__ float4 sC[NBASIS];

    const int h   = blockIdx.x;
    const int tid = threadIdx.x;

    if (tid < NLAYERS * NQ * 3) {
        const float th = params[h * NLAYERS * NQ * 3 + tid];
        float s, c;
        __sincosf(0.5f * th, &s, &c);
        gc[tid] = c;
        gs[tid] = s;
    }
    __syncthreads();

    if (tid < DIM) {
        float re[DIM], im[DIM];
        #pragma unroll
        for (int s = 0; s < DIM; s++) { re[s] = 0.f; im[s] = 0.f; }
        re[tid] = 1.f;

        for (int l = 0; l < NLAYERS; l++) {
            for (int w = 0; w < NQ; w++) {
                const int mask = 1 << (3 - w);
                const int gi = (l * NQ + w) * 3;
                const float cx = gc[gi + 0], sx = gs[gi + 0];
                const float cy = gc[gi + 1], sy = gs[gi + 1];
                const float cz = gc[gi + 2], sz = gs[gi + 2];
                #pragma unroll
                for (int s0 = 0; s0 < DIM; s0++) {
                    if (s0 & mask) continue;
                    const int s1 = s0 | mask;
                    float r0 = re[s0], i0 = im[s0], r1 = re[s1], i1 = im[s1];
                    float nr0 = cx * r0 + sx * i1;
                    float ni0 = cx * i0 - sx * r1;
                    float nr1 = sx * i0 + cx * r1;
                    float ni1 = -sx * r0 + cx * i1;
                    r0 = nr0; i0 = ni0; r1 = nr1; i1 = ni1;
                    nr0 = cy * r0 - sy * r1;
                    ni0 = cy * i0 - sy * i1;
                    nr1 = sy * r0 + cy * r1;
                    ni1 = sy * i0 + cy * i1;
                    r0 = nr0; i0 = ni0; r1 = nr1; i1 = ni1;
                    re[s0] = cz * r0 + sz * i0;
                    im[s0] = cz * i0 - sz * r0;
                    re[s1] = cz * r1 - sz * i1;
                    im[s1] = cz * i1 + sz * r1;
                }
            }
            #pragma unroll
            for (int e = 0; e < NQ; e++) {
                const int c = e, t = (e + 1) & 3;
                const int cm = 1 << (3 - c), tm = 1 << (3 - t);
                #pragma unroll
                for (int s = 0; s < DIM; s++) {
                    if ((s & cm) && !(s & tm)) {
                        const int s2 = s | tm;
                        float tr = re[s]; re[s] = re[s2]; re[s2] = tr;
                        float ti = im[s]; im[s] = im[s2]; im[s2] = ti;
                    }
                }
            }
        }
        #pragma unroll
        for (int s = 0; s < DIM; s++) { Ur[tid][s] = re[s]; Ui[tid][s] = im[s]; }
    }
    __syncthreads();

    {
        const int p = tid >> 4, q = tid & 15;
        float a0 = 0.f, a1 = 0.f, a2 = 0.f, a3 = 0.f;
        #pragma unroll
        for (int s = 0; s < DIM; s++) {
            float rr = Ur[p][s] * Ur[q][s] + Ui[p][s] * Ui[q][s];
            a0 += (s & 8) ? -rr : rr;
            a1 += (s & 4) ? -rr : rr;
            a2 += (s & 2) ? -rr : rr;
            a3 += (s & 1) ? -rr : rr;
        }
        A[0][tid] = a0; A[1][tid] = a1; A[2][tid] = a2; A[3][tid] = a3;
    }
    __syncthreads();

    if (tid < NBASIS) {
        int kw[4] = {tid / 27, (tid / 9) % 3, (tid / 3) % 3, tid % 3};
        float acc0 = 0.f, acc1 = 0.f, acc2 = 0.f, acc3 = 0.f;
        #pragma unroll
        for (int mm = 0; mm < 16; mm++) {
            int p = 0, q = 0;
            float wgt = 1.0f / 16.0f;
            #pragma unroll
            for (int w = 0; w < 4; w++) {
                const int opt = (mm >> w) & 1;
                const int kk = kw[w];
                int a, bb;
                if (kk == 0)      { a = opt; bb = opt; }
                else if (kk == 1) { a = opt; bb = opt; if (opt) wgt = -wgt; }
                else              { a = opt; bb = 1 - opt; }
                p |= a << (3 - w);
                q |= bb << (3 - w);
            }
            acc0 += wgt * A[0][p * 16 + q];
            acc1 += wgt * A[1][p * 16 + q];
            acc2 += wgt * A[2][p * 16 + q];
            acc3 += wgt * A[3][p * 16 + q];
        }
        sC[tid] = make_float4(acc0, acc1, acc2, acc3);
    }
    __syncthreads();

    // Emit fragment-ordered B (uint4 nt-pair layout)
    for (int e = tid; e < KS * 2 * 32; e += 256) {
        const int ks = e >> 6;
        const int np = (e >> 5) & 1;
        const int lane = e & 31;
        const int m = lane & 3, g = lane >> 2;

        float vv[2][2][2];   // [sub][dh][eps]
        #pragma unroll
        for (int sub = 0; sub < 2; sub++) {
            const int n = (2 * np + sub) * 8 + g;
            const float* wr = W + n * 32 + h * 4;   // W_out[n][h*4+q]
            #pragma unroll
            for (int dh = 0; dh < 2; dh++) {
                #pragma unroll
                for (int eps = 0; eps < 2; eps++) {
                    const int slot = 2 * ks + dh;
                    float val = 0.f;
                    if (slot <= 8) {
                        const float4 c = sC[9 * slot + (2 * m + eps)];
                        val = c.x * wr[0] + c.y * wr[1] + c.z * wr[2] + c.w * wr[3];
                    } else {
                        const int p = slot - 9;
                        const int q = (m == 0) ? eps : ((m == 1 && eps == 0) ? 2 : -1);
                        if (q >= 0) {
                            const float4 c = sC[9 * (3 * p + q) + 8];
                            val = c.x * wr[0] + c.y * wr[1] + c.z * wr[2] + c.w * wr[3];
                        }
                    }
                    vv[sub][dh][eps] = val;
                }
            }
        }
        g_Bf4[(h * KS + ks) * 64 + np * 32 + lane] =
            make_uint4(f2h2(vv[0][0][0], vv[0][0][1]),
                       f2h2(vv[0][1][0], vv[0][1][1]),
                       f2h2(vv[1][0][0], vv[1][0][1]),
                       f2h2(vv[1][1][0], vv[1][1][1]));
    }
}

// Build the 12 slot registers for one token from its c[4], s[4] (per-lane m).
__device__ __forceinline__ void build_slots(const float* c, const float* s, int m,
                                            uint32_t* S) {
    const float c2c3 = c[2] * c[3], c2s3 = c[2] * s[3];
    const float s2c3 = s[2] * c[3], s2s3 = s[2] * s[3];
    const float Px = (m & 2) ? ((m & 1) ? s[2] : c2c3) : ((m & 1) ? s[3] : 1.f);
    const float Py = (m & 2) ? ((m & 1) ? s2c3 : c2s3) : ((m & 1) ? c[2] : c[3]);
    const float Qx = (m & 2) ? 0.f : ((m & 1) ? s[1] * s2s3 : s2s3);
    const float Qy = (m == 0) ? c[1] * s2s3 : 0.f;

    const float A9[9] = {1.f, c[1], s[1], c[0], c[0] * c[1], c[0] * s[1],
                         s[0], s[0] * c[1], s[0] * s[1]};
    #pragma unroll
    for (int i = 0; i < 9; i++) S[i] = f2h2(A9[i] * Px, A9[i] * Py);
    S[9]  = f2h2(Qx, Qy);
    S[10] = f2h2(c[0] * Qx, c[0] * Qy);
    S[11] = f2h2(s[0] * Qx, s[0] * Qy);
}

// ---------------------------------------------------------------------------
// Main: NO shared memory, NO barriers, NO shfl. Each warp owns 32 tokens
// (2 m16-tiles sharing every B fragment load). Lane computes all 4 sincos of
// each of its 4 token-classes locally (MUFU is idle; MIO/L1 is the wall).
// ---------------------------------------------------------------------------
__global__ __launch_bounds__(128, 3) void qmha_mma(
    const float4* __restrict__ x,
    float*        __restrict__ out,
    const float*  __restrict__ bias)
{
    const int lane = threadIdx.x & 31;
    const int warp = threadIdx.x >> 5;
    const int m = lane & 3, g = lane >> 2;
    const int tbase = blockIdx.x * 128 + warp * 32;
    const int tok0 = tbase + g;            // tile0 rows 0-7
    const int tok1 = tbase + 8 + g;        // tile0 rows 8-15
    const int tok2 = tbase + 16 + g;       // tile1 rows 0-7
    const int tok3 = tbase + 24 + g;       // tile1 rows 8-15

    float acc[2][4][4];
    #pragma unroll
    for (int t = 0; t < 2; t++)
        #pragma unroll
        for (int nt = 0; nt < 4; nt++)
            #pragma unroll
            for (int r = 0; r < 4; r++) acc[t][nt][r] = 0.f;

    #pragma unroll 1
    for (int h = 0; h < NHEADS; h++) {
        uint32_t S[4][12];
        const int toks[4] = {tok0, tok1, tok2, tok3};
        #pragma unroll
        for (int cls = 0; cls < 4; cls++) {
            const float4 xv = x[toks[cls] * 8 + h];
            float c[4], s[4];
            __sincosf(xv.x, &s[0], &c[0]);
            __sincosf(xv.y, &s[1], &c[1]);
            __sincosf(xv.z, &s[2], &c[2]);
            __sincosf(xv.w, &s[3], &c[3]);
            build_slots(c, s, m, S[cls]);
        }

        const uint4* Bf = g_Bf4 + h * KS * 64 + lane;
        #pragma unroll
        for (int ks = 0; ks < KS; ks++) {
            const uint4 bA = __ldg(Bf + ks * 64);        // nt 0,1
            const uint4 bB = __ldg(Bf + ks * 64 + 32);   // nt 2,3
            #pragma unroll
            for (int t = 0; t < 2; t++) {
                const uint32_t a0 = S[2 * t + 0][2 * ks];
                const uint32_t a1 = S[2 * t + 1][2 * ks];
                const uint32_t a2 = S[2 * t + 0][2 * ks + 1];
                const uint32_t a3 = S[2 * t + 1][2 * ks + 1];
                mma16816(acc[t][0][0], acc[t][0][1], acc[t][0][2], acc[t][0][3],
                         a0, a1, a2, a3, bA.x, bA.y);
                mma16816(acc[t][1][0], acc[t][1][1], acc[t][1][2], acc[t][1][3],
                         a0, a1, a2, a3, bA.z, bA.w);
                mma16816(acc[t][2][0], acc[t][2][1], acc[t][2][2], acc[t][2][3],
                         a0, a1, a2, a3, bB.x, bB.y);
                mma16816(acc[t][3][0], acc[t][3][1], acc[t][3][2], acc[t][3][3],
                         a0, a1, a2, a3, bB.z, bB.w);
            }
        }
    }

    // epilogue: c0,c1 = (rowA, cols nt*8+2m,+1); c2,c3 = (rowB, same cols)
    #pragma unroll
    for (int t = 0; t < 2; t++) {
        const int tA = (t == 0) ? tok0 : tok2;
        const int tB = (t == 0) ? tok1 : tok3;
        #pragma unroll
        for (int nt = 0; nt < 4; nt++) {
            const int n0 = nt * 8 + 2 * m;
            const float2 bv = *(const float2*)(bias + n0);
            float2 oA; oA.x = acc[t][nt][0] + bv.x; oA.y = acc[t][nt][1] + bv.y;
            float2 oB; oB.x = acc[t][nt][2] + bv.x; oB.y = acc[t][nt][3] + bv.y;
            *(float2*)(out + tA * 32 + n0) = oA;
            *(float2*)(out + tB * 32 + n0) = oB;
        }
    }
}

extern "C" void kernel_launch(void* const* d_in, const int* in_sizes, int n_in,
                              void* d_out, int out_size) {
    const float* x      = (const float*)d_in[0];
    const float* params = (const float*)d_in[1];
    const float* W      = (const float*)d_in[2];
    const float* b      = (const float*)d_in[3];

    const int tokens = in_sizes[0] / EMBED;   // 131072

    qmha_precompute<<<NHEADS, 256>>>(params, W);

    const int blocks = tokens / 128;          // 1024 (128 tokens per block)
    qmha_mma<<<blocks, 128>>>((const float4*)x, (float*)d_out, b);
}

// round 16
// speedup vs baseline: 1.7551x; 1.0502x over previous
#include <cuda_runtime.h>
#include <cuda_fp16.h>
#include <cstdint>

#define NQ      4
#define DIM     16
#define NHEADS  8
#define NLAYERS 2
#define EMBED   32
#define NBASIS  81
#define KS      6                // 6 k-steps of 16 -> K=96 (12 slots)

// B operand in m16n8k16 fragment order, packed as uint4 covering an nt-PAIR:
// g_Bf4[(h*KS+ks)*2*32 + np*32 + lane] =
//   {x: half2(b0 of nt=2np), y: half2(b1 of nt=2np),
//    z: half2(b0 of nt=2np+1), w: half2(b1 of nt=2np+1)}
// where b0 = (M[k0][n],M[k0+1][n]), b1 = (M[k0+8][n],M[k0+9][n]),
// k0 = ks*16 + 2*(lane%4), n = nt*8 + lane/4.
__device__ uint4 g_Bf4[NHEADS * KS * 2 * 32];

// pack two f32 -> f16x2 (lo = first arg)
__device__ __forceinline__ uint32_t f2h2(float lo, float hi) {
    uint32_t r;
    asm("cvt.rn.f16x2.f32 %0, %1, %2;" : "=r"(r) : "f"(hi), "f"(lo));
    return r;
}

__device__ __forceinline__ void mma16816(float& d0, float& d1, float& d2, float& d3,
                                         uint32_t a0, uint32_t a1, uint32_t a2, uint32_t a3,
                                         uint32_t b0, uint32_t b1) {
    asm("mma.sync.aligned.m16n8k16.row.col.f32.f16.f16.f32 "
        "{%0,%1,%2,%3}, {%4,%5,%6,%7}, {%8,%9}, {%0,%1,%2,%3};"
        : "+f"(d0), "+f"(d1), "+f"(d2), "+f"(d3)
        : "r"(a0), "r"(a1), "r"(a2), "r"(a3), "r"(b0), "r"(b1));
}

// ---------------------------------------------------------------------------
// Precompute: per-head C pipeline (validated R8-R15), then emit B in the
// uint4 nt-pair fragment layout under the R14 slot basis-reordering.
// ---------------------------------------------------------------------------
__global__ void qmha_precompute(const float* __restrict__ params,
                                const float* __restrict__ W) {
    __shared__ float Ur[DIM][DIM];
    __shared__ float Ui[DIM][DIM];
    __shared__ float A[NQ][DIM * DIM];
    __shared__ float gc[NLAYERS * NQ * 3];
    __shared__ float gs[NLAYERS * NQ * 3];
    __shared__ float4 sC[NBASIS];

    const int h   = blockIdx.x;
    const int tid = threadIdx.x;

    if (tid < NLAYERS * NQ * 3) {
        const float th = params[h * NLAYERS * NQ * 3 + tid];
        float s, c;
        __sincosf(0.5f * th, &s, &c);
        gc[tid] = c;
        gs[tid] = s;
    }
    __syncthreads();

    if (tid < DIM) {
        float re[DIM], im[DIM];
        #pragma unroll
        for (int s = 0; s < DIM; s++) { re[s] = 0.f; im[s] = 0.f; }
        re[tid] = 1.f;

        for (int l = 0; l < NLAYERS; l++) {
            for (int w = 0; w < NQ; w++) {
                const int mask = 1 << (3 - w);
                const int gi = (l * NQ + w) * 3;
                const float cx = gc[gi + 0], sx = gs[gi + 0];
                const float cy = gc[gi + 1], sy = gs[gi + 1];
                const float cz = gc[gi + 2], sz = gs[gi + 2];
                #pragma unroll
                for (int s0 = 0; s0 < DIM; s0++) {
                    if (s0 & mask) continue;
                    const int s1 = s0 | mask;
                    float r0 = re[s0], i0 = im[s0], r1 = re[s1], i1 = im[s1];
                    float nr0 = cx * r0 + sx * i1;
                    float ni0 = cx * i0 - sx * r1;
                    float nr1 = sx * i0 + cx * r1;
                    float ni1 = -sx * r0 + cx * i1;
                    r0 = nr0; i0 = ni0; r1 = nr1; i1 = ni1;
                    nr0 = cy * r0 - sy * r1;
                    ni0 = cy * i0 - sy * i1;
                    nr1 = sy * r0 + cy * r1;
                    ni1 = sy * i0 + cy * i1;
                    r0 = nr0; i0 = ni0; r1 = nr1; i1 = ni1;
                    re[s0] = cz * r0 + sz * i0;
                    im[s0] = cz * i0 - sz * r0;
                    re[s1] = cz * r1 - sz * i1;
                    im[s1] = cz * i1 + sz * r1;
                }
            }
            #pragma unroll
            for (int e = 0; e < NQ; e++) {
                const int c = e, t = (e + 1) & 3;
                const int cm = 1 << (3 - c), tm = 1 << (3 - t);
                #pragma unroll
                for (int s = 0; s < DIM; s++) {
                    if ((s & cm) && !(s & tm)) {
                        const int s2 = s | tm;
                        float tr = re[s]; re[s] = re[s2]; re[s2] = tr;
                        float ti = im[s]; im[s] = im[s2]; im[s2] = ti;
                    }
                }
            }
        }
        #pragma unroll
        for (int s = 0; s < DIM; s++) { Ur[tid][s] = re[s]; Ui[tid][s] = im[s]; }
    }
    __syncthreads();

    {
        const int p = tid >> 4, q = tid & 15;
        float a0 = 0.f, a1 = 0.f, a2 = 0.f, a3 = 0.f;
        #pragma unroll
        for (int s = 0; s < DIM; s++) {
            float rr = Ur[p][s] * Ur[q][s] + Ui[p][s] * Ui[q][s];
            a0 += (s & 8) ? -rr : rr;
            a1 += (s & 4) ? -rr : rr;
            a2 += (s & 2) ? -rr : rr;
            a3 += (s & 1) ? -rr : rr;
        }
        A[0][tid] = a0; A[1][tid] = a1; A[2][tid] = a2; A[3][tid] = a3;
    }
    __syncthreads();

    if (tid < NBASIS) {
        int kw[4] = {tid / 27, (tid / 9) % 3, (tid / 3) % 3, tid % 3};
        float acc0 = 0.f, acc1 = 0.f, acc2 = 0.f, acc3 = 0.f;
        #pragma unroll
        for (int mm = 0; mm < 16; mm++) {
            int p = 0, q = 0;
            float wgt = 1.0f / 16.0f;
            #pragma unroll
            for (int w = 0; w < 4; w++) {
                const int opt = (mm >> w) & 1;
                const int kk = kw[w];
                int a, bb;
                if (kk == 0)      { a = opt; bb = opt; }
                else if (kk == 1) { a = opt; bb = opt; if (opt) wgt = -wgt; }
                else              { a = opt; bb = 1 - opt; }
                p |= a << (3 - w);
                q |= bb << (3 - w);
            }
            acc0 += wgt * A[0][p * 16 + q];
            acc1 += wgt * A[1][p * 16 + q];
            acc2 += wgt * A[2][p * 16 + q];
            acc3 += wgt * A[3][p * 16 + q];
        }
        sC[tid] = make_float4(acc0, acc1, acc2, acc3);
    }
    __syncthreads();

    // Emit fragment-ordered B (uint4 nt-pair layout)
    for (int e = tid; e < KS * 2 * 32; e += 256) {
        const int ks = e >> 6;
        const int np = (e >> 5) & 1;
        const int lane = e & 31;
        const int m = lane & 3, g = lane >> 2;

        float vv[2][2][2];   // [sub][dh][eps]
        #pragma unroll
        for (int sub = 0; sub < 2; sub++) {
            const int n = (2 * np + sub) * 8 + g;
            const float* wr = W + n * 32 + h * 4;   // W_out[n][h*4+q]
            #pragma unroll
            for (int dh = 0; dh < 2; dh++) {
                #pragma unroll
                for (int eps = 0; eps < 2; eps++) {
                    const int slot = 2 * ks + dh;
                    float val = 0.f;
                    if (slot <= 8) {
                        const float4 c = sC[9 * slot + (2 * m + eps)];
                        val = c.x * wr[0] + c.y * wr[1] + c.z * wr[2] + c.w * wr[3];
                    } else {
                        const int p = slot - 9;
                        const int q = (m == 0) ? eps : ((m == 1 && eps == 0) ? 2 : -1);
                        if (q >= 0) {
                            const float4 c = sC[9 * (3 * p + q) + 8];
                            val = c.x * wr[0] + c.y * wr[1] + c.z * wr[2] + c.w * wr[3];
                        }
                    }
                    vv[sub][dh][eps] = val;
                }
            }
        }
        g_Bf4[(h * KS + ks) * 64 + np * 32 + lane] =
            make_uint4(f2h2(vv[0][0][0], vv[0][0][1]),
                       f2h2(vv[0][1][0], vv[0][1][1]),
                       f2h2(vv[1][0][0], vv[1][0][1]),
                       f2h2(vv[1][1][0], vv[1][1][1]));
    }
}

// Build the 12 slot registers for one token from its c[4], s[4] (per-lane m).
__device__ __forceinline__ void build_slots(const float* c, const float* s, int m,
                                            uint32_t* S) {
    const float c2c3 = c[2] * c[3], c2s3 = c[2] * s[3];
    const float s2c3 = s[2] * c[3], s2s3 = s[2] * s[3];
    const float Px = (m & 2) ? ((m & 1) ? s[2] : c2c3) : ((m & 1) ? s[3] : 1.f);
    const float Py = (m & 2) ? ((m & 1) ? s2c3 : c2s3) : ((m & 1) ? c[2] : c[3]);
    const float Qx = (m & 2) ? 0.f : ((m & 1) ? s[1] * s2s3 : s2s3);
    const float Qy = (m == 0) ? c[1] * s2s3 : 0.f;

    const float A9[9] = {1.f, c[1], s[1], c[0], c[0] * c[1], c[0] * s[1],
                         s[0], s[0] * c[1], s[0] * s[1]};
    #pragma unroll
    for (int i = 0; i < 9; i++) S[i] = f2h2(A9[i] * Px, A9[i] * Py);
    S[9]  = f2h2(Qx, Qy);
    S[10] = f2h2(c[0] * Qx, c[0] * Qy);
    S[11] = f2h2(s[0] * Qx, s[0] * Qy);
}

// ---------------------------------------------------------------------------
// Main: NO shared memory, NO barriers, NO shfl. Each warp owns 32 tokens
// (2 m16-tiles sharing every B fragment load). B loads double-buffered so
// each ~L2-latency load overlaps a full MMA epoch. 4 blocks/SM (reg cap 128).
// ---------------------------------------------------------------------------
__global__ __launch_bounds__(128, 4) void qmha_mma(
    const float4* __restrict__ x,
    float*        __restrict__ out,
    const float*  __restrict__ bias)
{
    const int lane = threadIdx.x & 31;
    const int warp = threadIdx.x >> 5;
    const int m = lane & 3, g = lane >> 2;
    const int tbase = blockIdx.x * 128 + warp * 32;
    const int tok0 = tbase + g;            // tile0 rows 0-7
    const int tok1 = tbase + 8 + g;        // tile0 rows 8-15
    const int tok2 = tbase + 16 + g;       // tile1 rows 0-7
    const int tok3 = tbase + 24 + g;       // tile1 rows 8-15

    float acc[2][4][4];
    #pragma unroll
    for (int t = 0; t < 2; t++)
        #pragma unroll
        for (int nt = 0; nt < 4; nt++)
            #pragma unroll
            for (int r = 0; r < 4; r++) acc[t][nt][r] = 0.f;

    const uint4* BfL = g_Bf4 + lane;
    uint4 bA = __ldg(BfL);         // h=0, ks=0, nt 0,1
    uint4 bB = __ldg(BfL + 32);    // h=0, ks=0, nt 2,3

    #pragma unroll 1
    for (int h = 0; h < NHEADS; h++) {
        uint32_t S[4][12];
        const int toks[4] = {tok0, tok1, tok2, tok3};
        #pragma unroll
        for (int cls = 0; cls < 4; cls++) {
            const float4 xv = x[toks[cls] * 8 + h];
            float c[4], s[4];
            __sincosf(xv.x, &s[0], &c[0]);
            __sincosf(xv.y, &s[1], &c[1]);
            __sincosf(xv.z, &s[2], &c[2]);
            __sincosf(xv.w, &s[3], &c[3]);
            build_slots(c, s, m, S[cls]);
        }

        const uint4* Bf = BfL + h * KS * 64;
        #pragma unroll
        for (int ks = 0; ks < KS; ks++) {
            const uint4 cA = bA, cB = bB;
            // prefetch next epoch (next ks, or first of next head)
            const uint4* nxt = (ks + 1 < KS) ? (Bf + (ks + 1) * 64)
                                             : (BfL + ((h + 1) & 7) * KS * 64);
            bA = __ldg(nxt);
            bB = __ldg(nxt + 32);

            #pragma unroll
            for (int t = 0; t < 2; t++) {
                const uint32_t a0 = S[2 * t + 0][2 * ks];
                const uint32_t a1 = S[2 * t + 1][2 * ks];
                const uint32_t a2 = S[2 * t + 0][2 * ks + 1];
                const uint32_t a3 = S[2 * t + 1][2 * ks + 1];
                mma16816(acc[t][0][0], acc[t][0][1], acc[t][0][2], acc[t][0][3],
                         a0, a1, a2, a3, cA.x, cA.y);
                mma16816(acc[t][1][0], acc[t][1][1], acc[t][1][2], acc[t][1][3],
                         a0, a1, a2, a3, cA.z, cA.w);
                mma16816(acc[t][2][0], acc[t][2][1], acc[t][2][2], acc[t][2][3],
                         a0, a1, a2, a3, cB.x, cB.y);
                mma16816(acc[t][3][0], acc[t][3][1], acc[t][3][2], acc[t][3][3],
                         a0, a1, a2, a3, cB.z, cB.w);
            }
        }
    }

    // epilogue: c0,c1 = (rowA, cols nt*8+2m,+1); c2,c3 = (rowB, same cols)
    #pragma unroll
    for (int t = 0; t < 2; t++) {
        const int tA = (t == 0) ? tok0 : tok2;
        const int tB = (t == 0) ? tok1 : tok3;
        #pragma unroll
        for (int nt = 0; nt < 4; nt++) {
            const int n0 = nt * 8 + 2 * m;
            const float2 bv = *(const float2*)(bias + n0);
            float2 oA; oA.x = acc[t][nt][0] + bv.x; oA.y = acc[t][nt][1] + bv.y;
            float2 oB; oB.x = acc[t][nt][2] + bv.x; oB.y = acc[t][nt][3] + bv.y;
            *(float2*)(out + tA * 32 + n0) = oA;
            *(float2*)(out + tB * 32 + n0) = oB;
        }
    }
}

extern "C" void kernel_launch(void* const* d_in, const int* in_sizes, int n_in,
                              void* d_out, int out_size) {
    const float* x      = (const float*)d_in[0];
    const float* params = (const float*)d_in[1];
    const float* W      = (const float*)d_in[2];
    const float* b      = (const float*)d_in[3];

    const int tokens = in_sizes[0] / EMBED;   // 131072

    qmha_precompute<<<NHEADS, 256>>>(params, W);

    const int blocks = tokens / 128;          // 1024 (128 tokens per block)
    qmha_mma<<<blocks, 128>>>((const float4*)x, (float*)d_out, b);
}